// round 6
// baseline (speedup 1.0000x reference)
#include <cuda_runtime.h>
#include <cuda_fp16.h>
#include <cstdint>

// ============================================================================
// Portable PTX helpers (mma.sync / ldmatrix / cp.async only — no 'a'-gated ops)
// ============================================================================

__device__ __forceinline__ uint32_t smem_to_u32(const void* smem_ptr) {
    uint32_t addr;
    asm("{ .reg .u64 tmp; cvta.to.shared.u64 tmp, %1; cvt.u32.u64 %0, tmp; }"
        : "=r"(addr) : "l"(smem_ptr));
    return addr;
}

__device__ __forceinline__ void cp_async16(uint32_t dst, const void* src) {
    asm volatile("cp.async.cg.shared.global [%0], [%1], 16;"
                 :: "r"(dst), "l"(__cvta_generic_to_global(src)));
}
__device__ __forceinline__ void cp_commit() {
    asm volatile("cp.async.commit_group;" ::: "memory");
}
__device__ __forceinline__ void cp_wait0() {
    asm volatile("cp.async.wait_group 0;" ::: "memory");
}

__device__ __forceinline__ void ldmx4(uint32_t* r, uint32_t addr) {
    asm volatile("ldmatrix.sync.aligned.m8n8.x4.shared.b16 {%0,%1,%2,%3}, [%4];"
                 : "=r"(r[0]), "=r"(r[1]), "=r"(r[2]), "=r"(r[3]) : "r"(addr));
}

__device__ __forceinline__ void mma16816(float* c, const uint32_t* a, const uint32_t* b) {
    asm volatile(
        "mma.sync.aligned.m16n8k16.row.col.f32.f16.f16.f32 "
        "{%0,%1,%2,%3}, {%4,%5,%6,%7}, {%8,%9}, {%0,%1,%2,%3};"
        : "+f"(c[0]), "+f"(c[1]), "+f"(c[2]), "+f"(c[3])
        : "r"(a[0]), "r"(a[1]), "r"(a[2]), "r"(a[3]), "r"(b[0]), "r"(b[1]));
}

// ============================================================================
// Problem constants
// ============================================================================
static constexpr int DIN = 256;    // K
static constexpr int BM  = 128;    // CTA M tile
static constexpr int BN  = 256;    // CTA N tile
static constexpr int BK  = 32;     // K chunk (2 k16 steps)
static constexpr int NCHUNK = DIN / BK;  // 8

static constexpr int A_STRIDE = 80;    // 32 fp16 (64B) + 16B pad -> conflict-free ldmatrix
static constexpr int B_STRIDE = 528;   // 256 fp16 (512B) + 16B pad -> conflict-free ldmatrix
static constexpr int A_STAGE  = BM * A_STRIDE;   // 10240

// smem layout (dynamic, bytes)
static constexpr int SM_B    = 0;                   // 256 * 528 = 135168 (persistent, full K)
static constexpr int SM_A    = 135168;              // 4 stages * 10240 = 40960
static constexpr int SM_BIAS = 176128;              // 256 floats = 1024
static constexpr int SMEM_SZ = 177152;

// ============================================================================
// Device scratch (no allocation allowed -> __device__ globals)
// ============================================================================
__device__ float  g_bias[512];           // [0:256) combined bias c1, [256:512) out bias c2
__device__ float  g_W1[256 * 256];
__device__ __half g_Bh[512 * 256];       // fused weight, [n][k] row-major, fp16

// ============================================================================
// Prep kernels: grid 512 (row x col-half), block 128, 8 acc chains, unroll 16.
// ============================================================================

__device__ __forceinline__ float warp_sum(float v) {
#pragma unroll
    for (int o = 16; o > 0; o >>= 1) v += __shfl_xor_sync(0xffffffffu, v, o);
    return v;
}

// Block (o, h): W1[o, h*128 + tid] = sum_i (gate*Wc[o,i]) * Wp[i, col].
// h==0 block also computes c1[o] and (o%32==0) the gate outputs.
__global__ void __launch_bounds__(128, 8)
prep_w1(const float* __restrict__ Wc, const float* __restrict__ Wp,
        const float* __restrict__ bp,
        const float* __restrict__ pre, const float* __restrict__ post,
        float* __restrict__ out_tail) {
    __shared__ float sWc[256];
    __shared__ float sRed[4];
    __shared__ float sGate;
    const int o   = blockIdx.x >> 1;
    const int h   = blockIdx.x & 1;
    const int tid = threadIdx.x;
    const int col = h * 128 + tid;
    const int ko  = o >> 5;

    if (tid < 32) {
        float a = pre[ko * 256 + tid];
        float b = post[ko * 32 + tid];
        float sp = warp_sum(a * a);
        float sq = warp_sum(b * b);
        float np = fmaxf(sqrtf(sp), 1e-12f);
        float nq = fmaxf(sqrtf(sq), 1e-12f);
        float d  = warp_sum((a / np) * (b / nq));
        if (tid == 0) {
            float align = 1.0f / (1.0f + expf(-d));
            float g = (align >= 0.3f) ? align : 0.0f;
            sGate = g;
            if ((o & 31) == 0 && h == 0) {
                out_tail[ko] = g;          // alignments
                out_tail[8 + ko] = 1.0f;   // allocation_mask
            }
        }
    }
    __syncthreads();
    const float g = sGate;
    {
        float w0 = Wc[o * 256 + tid] * g;
        float w1 = Wc[o * 256 + 128 + tid] * g;
        sWc[tid] = w0;
        sWc[128 + tid] = w1;
    }
    __syncthreads();

    float acc[8] = {0.f, 0.f, 0.f, 0.f, 0.f, 0.f, 0.f, 0.f};
#pragma unroll 16
    for (int i = 0; i < 256; ++i)
        acc[i & 7] += sWc[i] * Wp[i * 256 + col];
    float r = ((acc[0] + acc[1]) + (acc[2] + acc[3])) +
              ((acc[4] + acc[5]) + (acc[6] + acc[7]));
    g_W1[o * 256 + col] = r;
    g_Bh[o * 256 + col] = __float2half_rn(r);

    if (h == 0) {
        float p = sWc[tid] * bp[tid] + sWc[128 + tid] * bp[128 + tid];
        p = warp_sum(p);
        if ((tid & 31) == 0) sRed[tid >> 5] = p;
        __syncthreads();
        if (tid == 0)
            g_bias[o] = (sRed[0] + sRed[1]) + (sRed[2] + sRed[3]);
    }
}

// Block (o, h): W2[o, col] = sum_i Wo[o,i] * W1[i, col]; h==0 computes c2[o].
__global__ void __launch_bounds__(128, 8)
prep_w2(const float* __restrict__ Wo, const float* __restrict__ bo) {
    __shared__ float sWo[256];
    __shared__ float sRed[4];
    const int o   = blockIdx.x >> 1;
    const int h   = blockIdx.x & 1;
    const int tid = threadIdx.x;
    const int col = h * 128 + tid;

    sWo[tid]       = Wo[o * 256 + tid];
    sWo[128 + tid] = Wo[o * 256 + 128 + tid];
    __syncthreads();

    float acc[8] = {0.f, 0.f, 0.f, 0.f, 0.f, 0.f, 0.f, 0.f};
#pragma unroll 16
    for (int i = 0; i < 256; ++i)
        acc[i & 7] += sWo[i] * g_W1[i * 256 + col];
    float r = ((acc[0] + acc[1]) + (acc[2] + acc[3])) +
              ((acc[4] + acc[5]) + (acc[6] + acc[7]));
    g_Bh[(256 + o) * 256 + col] = __float2half_rn(r);

    if (h == 0) {
        float p = sWo[tid] * g_bias[tid] + sWo[128 + tid] * g_bias[128 + tid];
        p = warp_sum(p);
        if ((tid & 31) == 0) sRed[tid >> 5] = p;
        __syncthreads();
        if (tid == 0)
            g_bias[256 + o] = (sRed[0] + sRed[1]) + (sRed[2] + sRed[3]) + bo[o];
    }
}

// ============================================================================
// Main fused GEMM: C[131072 x 512] = x[131072 x 256] @ B^T, single fp16 pass,
// HMMA m16n8k16, fp32 accumulate.
// CTA: 128x256, 16 warps (4M x 4N, warp tile 32x64), block 512, 1 CTA/SM.
// B persistent in smem. A: LDG->regs (prefetch distance 2) -> fp16 -> STS into
// a 4-stage smem ring. One __syncthreads per chunk (reuse distance 4 is safe:
// STS(c) on stage s occurs >= 3 syncs after all warps' MMA(c-4) on s).
// ============================================================================
__global__ void __launch_bounds__(512, 1)
fused_main(const float* __restrict__ x, float* __restrict__ out, int Brows) {
    extern __shared__ char smem[];
    const uint32_t sb = smem_to_u32(smem);
    const int tid  = threadIdx.x;
    const int wid  = tid >> 5, lane = tid & 31;
    const int nt   = blockIdx.x & 1;        // 0: combined cols, 1: out cols
    const int mt   = blockIdx.x >> 1;       // M-tile
    const int wm   = wid & 3;               // 4 M-warps of 32 rows
    const int wn   = wid >> 2;               // 4 N-warps of 64 cols

    const float*  xbase = x + (size_t)mt * BM * DIN;
    const __half* Bg    = g_Bh + (size_t)nt * BN * DIN;

    // ---- persistent B tile (256 rows x full K) + bias via cp.async ----
    {
        const uint32_t bd = sb + SM_B;
#pragma unroll
        for (int i = 0; i < 16; ++i) {
            int idx = tid + 512 * i;            // 8192 x 16B
            int row = idx >> 5, kseg = idx & 31;
            cp_async16(bd + row * B_STRIDE + kseg * 16, Bg + row * DIN + kseg * 8);
        }
        if (tid < 64)
            cp_async16(sb + SM_BIAS + tid * 16, g_bias + nt * BN + tid * 4);
        cp_commit();
    }

    float acc[2][8][4];
#pragma unroll
    for (int m = 0; m < 2; m++)
#pragma unroll
        for (int n = 0; n < 8; n++)
#pragma unroll
            for (int k = 0; k < 4; k++) acc[m][n][k] = 0.f;

    // per-thread x prefetch: 2 float4 per chunk, lookahead 2 chunks
    const int prow  = tid >> 2;                  // row 0..127
    const int pseg0 = (tid & 3) * 2;             // segs {0,1},{2,3},{4,5},{6,7}
    const float* xrow = xbase + prow * DIN + pseg0 * 4;
    float4 pre[2][2];
#pragma unroll
    for (int j = 0; j < 2; ++j) {
        pre[0][j] = *(const float4*)(xrow + 0 * BK + j * 4);
        pre[1][j] = *(const float4*)(xrow + 1 * BK + j * 4);
    }

    const int arow  = wm * 32 + (lane & 15);
    const uint32_t acolb = ((lane >> 4) & 1) * 16;
    const int brow0 = wn * 64 + ((lane & 7) | ((lane >> 4) << 3));
    const uint32_t bcolb = ((lane >> 3) & 1) * 16;

#pragma unroll 1
    for (int c = 0; c < NCHUNK; ++c) {
        const int s = c & 3;
        const int slot = c & 1;

        // ---- convert prefetched fp32 -> fp16, STS to A stage s ----
        {
            char* As = smem + SM_A + s * A_STAGE;
#pragma unroll
            for (int j = 0; j < 2; ++j) {
                float4 v = pre[slot][j];
                __half h0 = __float2half_rn(v.x), h1 = __float2half_rn(v.y);
                __half h2 = __float2half_rn(v.z), h3 = __float2half_rn(v.w);
                uint2 hp;
                hp.x = (uint32_t)__half_as_ushort(h0) | ((uint32_t)__half_as_ushort(h1) << 16);
                hp.y = (uint32_t)__half_as_ushort(h2) | ((uint32_t)__half_as_ushort(h3) << 16);
                *(uint2*)(As + prow * A_STRIDE + (pseg0 + j) * 8) = hp;
            }
        }
        if (c == 0) cp_wait0();     // B + bias resident before first ldmatrix
        __syncthreads();

        // ---- prefetch chunk c+2 into the slot just freed ----
        if (c + 2 < NCHUNK) {
#pragma unroll
            for (int j = 0; j < 2; ++j)
                pre[slot][j] = *(const float4*)(xrow + (c + 2) * BK + j * 4);
        }

        // ---- 2 k16 steps of MMA ----
        const uint32_t abase = sb + SM_A + s * A_STAGE;
        const uint32_t bks   = sb + SM_B + (uint32_t)(c * 64);   // c*32 halves = c*64 bytes
#pragma unroll
        for (int ks = 0; ks < 2; ++ks) {
            uint32_t af[2][4], bf[4][4];
#pragma unroll
            for (int m = 0; m < 2; ++m)
                ldmx4(af[m], abase + (uint32_t)((arow + m * 16) * A_STRIDE) + acolb + ks * 32);
#pragma unroll
            for (int p = 0; p < 4; ++p)
                ldmx4(bf[p], bks + (uint32_t)((brow0 + p * 16) * B_STRIDE) + bcolb + ks * 32);
#pragma unroll
            for (int m = 0; m < 2; ++m)
#pragma unroll
                for (int n = 0; n < 8; ++n)
                    mma16816(acc[m][n], af[m], &bf[n >> 1][(n & 1) * 2]);
        }
    }

    // ---- epilogue: add fused bias (smem), write this CTA's output half ----
    const float* bias_s = (const float*)(smem + SM_BIAS);
    // nt==0 -> combined block (second Brows*256 of out); nt==1 -> out block (first)
    float* hbase = out + (nt ? (size_t)0 : (size_t)Brows * 256);
#pragma unroll
    for (int m = 0; m < 2; ++m) {
        const int row = mt * BM + wm * 32 + m * 16 + (lane >> 2);
        float* rp = hbase + (size_t)row * 256;
#pragma unroll
        for (int n = 0; n < 8; ++n) {
            const int ln = wn * 64 + n * 8 + (lane & 3) * 2;   // 0..255 column
            const float b0 = bias_s[ln], b1 = bias_s[ln + 1];
            *(float2*)(rp + ln)           = make_float2(acc[m][n][0] + b0, acc[m][n][1] + b1);
            *(float2*)(rp + ln + 8 * 256) = make_float2(acc[m][n][2] + b0, acc[m][n][3] + b1);
        }
    }
}

// ============================================================================
// kernel_launch
// ============================================================================
extern "C" void kernel_launch(void* const* d_in, const int* in_sizes, int n_in,
                              void* d_out, int out_size) {
    const float* x    = (const float*)d_in[0];
    const float* Wp   = (const float*)d_in[1];
    const float* bp   = (const float*)d_in[2];
    const float* pre  = (const float*)d_in[3];
    const float* post = (const float*)d_in[4];
    const float* Wc   = (const float*)d_in[5];
    const float* Wo   = (const float*)d_in[6];
    const float* bo   = (const float*)d_in[7];
    float* out = (float*)d_out;
    const int Brows = in_sizes[0] / 256;   // 131072

    cudaFuncSetAttribute(fused_main, cudaFuncAttributeMaxDynamicSharedMemorySize, SMEM_SZ);

    prep_w1<<<512, 128>>>(Wc, Wp, bp, pre, post, out + (size_t)2 * Brows * 256);
    prep_w2<<<512, 128>>>(Wo, bo);
    fused_main<<<(Brows / BM) * 2, 512, SMEM_SZ>>>(x, out, Brows);
}

// round 7
// speedup vs baseline: 1.1824x; 1.1824x over previous
#include <cuda_runtime.h>
#include <cuda_fp16.h>
#include <cstdint>

// ============================================================================
// Portable PTX helpers (mma.sync / ldmatrix / cp.async only — no 'a'-gated ops)
// ============================================================================

__device__ __forceinline__ uint32_t smem_to_u32(const void* smem_ptr) {
    uint32_t addr;
    asm("{ .reg .u64 tmp; cvta.to.shared.u64 tmp, %1; cvt.u32.u64 %0, tmp; }"
        : "=r"(addr) : "l"(smem_ptr));
    return addr;
}

__device__ __forceinline__ void cp_async16(uint32_t dst, const void* src) {
    asm volatile("cp.async.cg.shared.global [%0], [%1], 16;"
                 :: "r"(dst), "l"(__cvta_generic_to_global(src)));
}
__device__ __forceinline__ void cp_commit() {
    asm volatile("cp.async.commit_group;" ::: "memory");
}
__device__ __forceinline__ void cp_wait0() {
    asm volatile("cp.async.wait_group 0;" ::: "memory");
}

__device__ __forceinline__ void ldmx4(uint32_t* r, uint32_t addr) {
    asm volatile("ldmatrix.sync.aligned.m8n8.x4.shared.b16 {%0,%1,%2,%3}, [%4];"
                 : "=r"(r[0]), "=r"(r[1]), "=r"(r[2]), "=r"(r[3]) : "r"(addr));
}

__device__ __forceinline__ void mma16816(float* c, const uint32_t* a, const uint32_t* b) {
    asm volatile(
        "mma.sync.aligned.m16n8k16.row.col.f32.f16.f16.f32 "
        "{%0,%1,%2,%3}, {%4,%5,%6,%7}, {%8,%9}, {%0,%1,%2,%3};"
        : "+f"(c[0]), "+f"(c[1]), "+f"(c[2]), "+f"(c[3])
        : "r"(a[0]), "r"(a[1]), "r"(a[2]), "r"(a[3]), "r"(b[0]), "r"(b[1]));
}

// ============================================================================
// Problem constants
// ============================================================================
static constexpr int DIN = 256;    // K
static constexpr int BM  = 128;    // CTA M tile
static constexpr int BN  = 256;    // CTA N tile
static constexpr int BK  = 32;     // K chunk (2 k16 steps)
static constexpr int NCHUNK = DIN / BK;  // 8

static constexpr int A_STRIDE = 80;    // 32 fp16 (64B) + 16B pad -> conflict-free ldmatrix
static constexpr int B_STRIDE = 528;   // 256 fp16 (512B) + 16B pad -> conflict-free ldmatrix

// smem layout (dynamic, bytes) — R5 proven layout (2-stage A ring)
static constexpr int SM_B    = 0;                   // 256 * 528 = 135168 (persistent, full K)
static constexpr int SM_A    = 135168;              // 2 stages * 128*80 = 20480
static constexpr int SM_BIAS = 155648;              // 256 floats = 1024
static constexpr int SMEM_SZ = 156672;

// ============================================================================
// Device scratch (no allocation allowed -> __device__ globals)
// ============================================================================
__device__ float  g_bias[512];           // [0:256) combined bias c1, [256:512) out bias c2
__device__ float  g_W1[256 * 256];
__device__ __half g_Bh[512 * 256];       // fused weight, [n][k] row-major, fp16

// ============================================================================
// Prep kernels (R6 measured-good): grid 512 (row x col-half), block 128,
// 8 acc chains, unroll 16.
// ============================================================================

__device__ __forceinline__ float warp_sum(float v) {
#pragma unroll
    for (int o = 16; o > 0; o >>= 1) v += __shfl_xor_sync(0xffffffffu, v, o);
    return v;
}

// Block (o, h): W1[o, h*128 + tid] = sum_i (gate*Wc[o,i]) * Wp[i, col].
// h==0 block also computes c1[o] and (o%32==0) the gate outputs.
__global__ void __launch_bounds__(128, 8)
prep_w1(const float* __restrict__ Wc, const float* __restrict__ Wp,
        const float* __restrict__ bp,
        const float* __restrict__ pre, const float* __restrict__ post,
        float* __restrict__ out_tail) {
    __shared__ float sWc[256];
    __shared__ float sRed[4];
    __shared__ float sGate;
    const int o   = blockIdx.x >> 1;
    const int h   = blockIdx.x & 1;
    const int tid = threadIdx.x;
    const int col = h * 128 + tid;
    const int ko  = o >> 5;

    if (tid < 32) {
        float a = pre[ko * 256 + tid];
        float b = post[ko * 32 + tid];
        float sp = warp_sum(a * a);
        float sq = warp_sum(b * b);
        float np = fmaxf(sqrtf(sp), 1e-12f);
        float nq = fmaxf(sqrtf(sq), 1e-12f);
        float d  = warp_sum((a / np) * (b / nq));
        if (tid == 0) {
            float align = 1.0f / (1.0f + expf(-d));
            float g = (align >= 0.3f) ? align : 0.0f;
            sGate = g;
            if ((o & 31) == 0 && h == 0) {
                out_tail[ko] = g;          // alignments
                out_tail[8 + ko] = 1.0f;   // allocation_mask
            }
        }
    }
    __syncthreads();
    const float g = sGate;
    {
        float w0 = Wc[o * 256 + tid] * g;
        float w1 = Wc[o * 256 + 128 + tid] * g;
        sWc[tid] = w0;
        sWc[128 + tid] = w1;
    }
    __syncthreads();

    float acc[8] = {0.f, 0.f, 0.f, 0.f, 0.f, 0.f, 0.f, 0.f};
#pragma unroll 16
    for (int i = 0; i < 256; ++i)
        acc[i & 7] += sWc[i] * Wp[i * 256 + col];
    float r = ((acc[0] + acc[1]) + (acc[2] + acc[3])) +
              ((acc[4] + acc[5]) + (acc[6] + acc[7]));
    g_W1[o * 256 + col] = r;
    g_Bh[o * 256 + col] = __float2half_rn(r);

    if (h == 0) {
        float p = sWc[tid] * bp[tid] + sWc[128 + tid] * bp[128 + tid];
        p = warp_sum(p);
        if ((tid & 31) == 0) sRed[tid >> 5] = p;
        __syncthreads();
        if (tid == 0)
            g_bias[o] = (sRed[0] + sRed[1]) + (sRed[2] + sRed[3]);
    }
}

// Block (o, h): W2[o, col] = sum_i Wo[o,i] * W1[i, col]; h==0 computes c2[o].
__global__ void __launch_bounds__(128, 8)
prep_w2(const float* __restrict__ Wo, const float* __restrict__ bo) {
    __shared__ float sWo[256];
    __shared__ float sRed[4];
    const int o   = blockIdx.x >> 1;
    const int h   = blockIdx.x & 1;
    const int tid = threadIdx.x;
    const int col = h * 128 + tid;

    sWo[tid]       = Wo[o * 256 + tid];
    sWo[128 + tid] = Wo[o * 256 + 128 + tid];
    __syncthreads();

    float acc[8] = {0.f, 0.f, 0.f, 0.f, 0.f, 0.f, 0.f, 0.f};
#pragma unroll 16
    for (int i = 0; i < 256; ++i)
        acc[i & 7] += sWo[i] * g_W1[i * 256 + col];
    float r = ((acc[0] + acc[1]) + (acc[2] + acc[3])) +
              ((acc[4] + acc[5]) + (acc[6] + acc[7]));
    g_Bh[(256 + o) * 256 + col] = __float2half_rn(r);

    if (h == 0) {
        float p = sWo[tid] * g_bias[tid] + sWo[128 + tid] * g_bias[128 + tid];
        p = warp_sum(p);
        if ((tid & 31) == 0) sRed[tid >> 5] = p;
        __syncthreads();
        if (tid == 0)
            g_bias[256 + o] = (sRed[0] + sRed[1]) + (sRed[2] + sRed[3]) + bo[o];
    }
}

// ============================================================================
// Main fused GEMM (R5 measured-good version, verbatim):
// C[131072 x 512] = x[131072 x 256] @ B^T, single fp16 pass, HMMA m16n8k16,
// fp32 accumulate. CTA: 128x256, 16 warps (4M x 4N, warp tile 32x64).
// B persistent in smem. A: LDG->regs (static pre[2]) -> fp16 -> STS,
// 2-stage ring, prefetch distance 1, one __syncthreads per chunk.
// ============================================================================
__global__ void __launch_bounds__(512, 1)
fused_main(const float* __restrict__ x, float* __restrict__ out, int Brows) {
    extern __shared__ char smem[];
    const uint32_t sb = smem_to_u32(smem);
    const int tid  = threadIdx.x;
    const int wid  = tid >> 5, lane = tid & 31;
    const int nt   = blockIdx.x & 1;        // 0: combined cols, 1: out cols
    const int mt   = blockIdx.x >> 1;       // M-tile
    const int wm   = wid & 3;               // 4 M-warps of 32 rows
    const int wn   = wid >> 2;              // 4 N-warps of 64 cols

    const float*  xbase = x + (size_t)mt * BM * DIN;
    const __half* Bg    = g_Bh + (size_t)nt * BN * DIN;

    // ---- persistent B tile (256 rows x full K) + bias via cp.async ----
    {
        const uint32_t bd = sb + SM_B;
#pragma unroll
        for (int i = 0; i < 16; ++i) {
            int idx = tid + 512 * i;            // 8192 x 16B
            int row = idx >> 5, kseg = idx & 31;
            cp_async16(bd + row * B_STRIDE + kseg * 16, Bg + row * DIN + kseg * 8);
        }
        if (tid < 64)
            cp_async16(sb + SM_BIAS + tid * 16, g_bias + nt * BN + tid * 4);
        cp_commit();
    }

    float acc[2][8][4];
#pragma unroll
    for (int m = 0; m < 2; m++)
#pragma unroll
        for (int n = 0; n < 8; n++)
#pragma unroll
            for (int k = 0; k < 4; k++) acc[m][n][k] = 0.f;

    // per-thread x prefetch: 2 float4 per chunk (static indexing)
    const int prow  = tid >> 2;                  // row 0..127
    const int pseg0 = (tid & 3) * 2;             // segs {0,1},{2,3},{4,5},{6,7}
    float4 pre[2];
#pragma unroll
    for (int j = 0; j < 2; ++j)
        pre[j] = *(const float4*)(xbase + prow * DIN + (pseg0 + j) * 4);

    const int arow  = wm * 32 + (lane & 15);
    const uint32_t acolb = ((lane >> 4) & 1) * 16;
    const int brow0 = wn * 64 + ((lane & 7) | ((lane >> 4) << 3));
    const uint32_t bcolb = ((lane >> 3) & 1) * 16;

#pragma unroll 1
    for (int c = 0; c < NCHUNK; ++c) {
        const int s = c & 1;

        // ---- convert prefetched fp32 -> fp16, STS to A stage s ----
        {
            char* As = smem + SM_A + s * (BM * A_STRIDE);
#pragma unroll
            for (int j = 0; j < 2; ++j) {
                __half h0 = __float2half_rn(pre[j].x), h1 = __float2half_rn(pre[j].y);
                __half h2 = __float2half_rn(pre[j].z), h3 = __float2half_rn(pre[j].w);
                uint2 hp;
                hp.x = (uint32_t)__half_as_ushort(h0) | ((uint32_t)__half_as_ushort(h1) << 16);
                hp.y = (uint32_t)__half_as_ushort(h2) | ((uint32_t)__half_as_ushort(h3) << 16);
                *(uint2*)(As + prow * A_STRIDE + (pseg0 + j) * 8) = hp;
            }
        }
        if (c == 0) cp_wait0();     // B + bias resident before first ldmatrix
        __syncthreads();

        // ---- prefetch next chunk (LDG in flight under the MMAs) ----
        if (c + 1 < NCHUNK) {
#pragma unroll
            for (int j = 0; j < 2; ++j)
                pre[j] = *(const float4*)(xbase + prow * DIN + (c + 1) * BK + (pseg0 + j) * 4);
        }

        // ---- 2 k16 steps of MMA ----
        const uint32_t abase = sb + SM_A + s * (BM * A_STRIDE);
        const uint32_t bks   = sb + SM_B + (uint32_t)(c * 64);   // c*32 halves = c*64 bytes
#pragma unroll
        for (int ks = 0; ks < 2; ++ks) {
            uint32_t af[2][4], bf[4][4];
#pragma unroll
            for (int m = 0; m < 2; ++m)
                ldmx4(af[m], abase + (uint32_t)((arow + m * 16) * A_STRIDE) + acolb + ks * 32);
#pragma unroll
            for (int p = 0; p < 4; ++p)
                ldmx4(bf[p], bks + (uint32_t)((brow0 + p * 16) * B_STRIDE) + bcolb + ks * 32);
#pragma unroll
            for (int m = 0; m < 2; ++m)
#pragma unroll
                for (int n = 0; n < 8; ++n)
                    mma16816(acc[m][n], af[m], &bf[n >> 1][(n & 1) * 2]);
        }
    }

    // ---- epilogue: add fused bias (smem), write this CTA's output half ----
    const float* bias_s = (const float*)(smem + SM_BIAS);
    // nt==0 -> combined block (second Brows*256 of out); nt==1 -> out block (first)
    float* hbase = out + (nt ? (size_t)0 : (size_t)Brows * 256);
#pragma unroll
    for (int m = 0; m < 2; ++m) {
        const int row = mt * BM + wm * 32 + m * 16 + (lane >> 2);
        float* rp = hbase + (size_t)row * 256;
#pragma unroll
        for (int n = 0; n < 8; ++n) {
            const int ln = wn * 64 + n * 8 + (lane & 3) * 2;   // 0..255 column
            const float b0 = bias_s[ln], b1 = bias_s[ln + 1];
            *(float2*)(rp + ln)           = make_float2(acc[m][n][0] + b0, acc[m][n][1] + b1);
            *(float2*)(rp + ln + 8 * 256) = make_float2(acc[m][n][2] + b0, acc[m][n][3] + b1);
        }
    }
}

// ============================================================================
// kernel_launch
// ============================================================================
extern "C" void kernel_launch(void* const* d_in, const int* in_sizes, int n_in,
                              void* d_out, int out_size) {
    const float* x    = (const float*)d_in[0];
    const float* Wp   = (const float*)d_in[1];
    const float* bp   = (const float*)d_in[2];
    const float* pre  = (const float*)d_in[3];
    const float* post = (const float*)d_in[4];
    const float* Wc   = (const float*)d_in[5];
    const float* Wo   = (const float*)d_in[6];
    const float* bo   = (const float*)d_in[7];
    float* out = (float*)d_out;
    const int Brows = in_sizes[0] / 256;   // 131072

    cudaFuncSetAttribute(fused_main, cudaFuncAttributeMaxDynamicSharedMemorySize, SMEM_SZ);

    prep_w1<<<512, 128>>>(Wc, Wp, bp, pre, post, out + (size_t)2 * Brows * 256);
    prep_w2<<<512, 128>>>(Wo, bo);
    fused_main<<<(Brows / BM) * 2, 512, SMEM_SZ>>>(x, out, Brows);
}

// round 8
// speedup vs baseline: 1.2141x; 1.0269x over previous
#include <cuda_runtime.h>
#include <cuda_fp16.h>
#include <cstdint>

// ============================================================================
// Portable PTX helpers (mma.sync / ldmatrix / cp.async only — no 'a'-gated ops)
// ============================================================================

__device__ __forceinline__ uint32_t smem_to_u32(const void* smem_ptr) {
    uint32_t addr;
    asm("{ .reg .u64 tmp; cvta.to.shared.u64 tmp, %1; cvt.u32.u64 %0, tmp; }"
        : "=r"(addr) : "l"(smem_ptr));
    return addr;
}

__device__ __forceinline__ void cp_async16(uint32_t dst, const void* src) {
    asm volatile("cp.async.cg.shared.global [%0], [%1], 16;"
                 :: "r"(dst), "l"(__cvta_generic_to_global(src)));
}
__device__ __forceinline__ void cp_commit() {
    asm volatile("cp.async.commit_group;" ::: "memory");
}
__device__ __forceinline__ void cp_wait0() {
    asm volatile("cp.async.wait_group 0;" ::: "memory");
}

__device__ __forceinline__ void ldmx4(uint32_t* r, uint32_t addr) {
    asm volatile("ldmatrix.sync.aligned.m8n8.x4.shared.b16 {%0,%1,%2,%3}, [%4];"
                 : "=r"(r[0]), "=r"(r[1]), "=r"(r[2]), "=r"(r[3]) : "r"(addr));
}

__device__ __forceinline__ void mma16816(float* c, const uint32_t* a, const uint32_t* b) {
    asm volatile(
        "mma.sync.aligned.m16n8k16.row.col.f32.f16.f16.f32 "
        "{%0,%1,%2,%3}, {%4,%5,%6,%7}, {%8,%9}, {%0,%1,%2,%3};"
        : "+f"(c[0]), "+f"(c[1]), "+f"(c[2]), "+f"(c[3])
        : "r"(a[0]), "r"(a[1]), "r"(a[2]), "r"(a[3]), "r"(b[0]), "r"(b[1]));
}

// ============================================================================
// Problem constants
// ============================================================================
static constexpr int DIN = 256;    // K
static constexpr int BM  = 128;    // CTA M tile
static constexpr int BN  = 256;    // CTA N tile
static constexpr int BK  = 64;     // K chunk (4 k16 steps) — halves sync count
static constexpr int NCHUNK = DIN / BK;  // 4

static constexpr int A_STRIDE = 144;   // 64 fp16 (128B) + 16B pad -> conflict-free (4r mod 32)
static constexpr int B_STRIDE = 528;   // 256 fp16 (512B) + 16B pad -> conflict-free
static constexpr int A_STAGE  = BM * A_STRIDE;   // 18432

// smem layout (dynamic, bytes)
static constexpr int SM_B    = 0;                   // 256 * 528 = 135168 (persistent, full K)
static constexpr int SM_A    = 135168;              // 2 stages * 18432 = 36864
static constexpr int SM_BIAS = 172032;              // 256 floats = 1024
static constexpr int SMEM_SZ = 173056;

// ============================================================================
// Device scratch (no allocation allowed -> __device__ globals)
// ============================================================================
__device__ float  g_bias[512];           // [0:256) combined bias c1, [256:512) out bias c2
__device__ float  g_W1[256 * 256];
__device__ __half g_Bh[512 * 256];       // fused weight, [n][k] row-major, fp16

// ============================================================================
// Prep kernels (measured-good): grid 512 (row x col-half), block 128,
// 8 acc chains, unroll 16.
// ============================================================================

__device__ __forceinline__ float warp_sum(float v) {
#pragma unroll
    for (int o = 16; o > 0; o >>= 1) v += __shfl_xor_sync(0xffffffffu, v, o);
    return v;
}

// Block (o, h): W1[o, h*128 + tid] = sum_i (gate*Wc[o,i]) * Wp[i, col].
// h==0 block also computes c1[o] and (o%32==0) the gate outputs.
__global__ void __launch_bounds__(128, 8)
prep_w1(const float* __restrict__ Wc, const float* __restrict__ Wp,
        const float* __restrict__ bp,
        const float* __restrict__ pre, const float* __restrict__ post,
        float* __restrict__ out_tail) {
    __shared__ float sWc[256];
    __shared__ float sRed[4];
    __shared__ float sGate;
    const int o   = blockIdx.x >> 1;
    const int h   = blockIdx.x & 1;
    const int tid = threadIdx.x;
    const int col = h * 128 + tid;
    const int ko  = o >> 5;

    if (tid < 32) {
        float a = pre[ko * 256 + tid];
        float b = post[ko * 32 + tid];
        float sp = warp_sum(a * a);
        float sq = warp_sum(b * b);
        float np = fmaxf(sqrtf(sp), 1e-12f);
        float nq = fmaxf(sqrtf(sq), 1e-12f);
        float d  = warp_sum((a / np) * (b / nq));
        if (tid == 0) {
            float align = 1.0f / (1.0f + expf(-d));
            float g = (align >= 0.3f) ? align : 0.0f;
            sGate = g;
            if ((o & 31) == 0 && h == 0) {
                out_tail[ko] = g;          // alignments
                out_tail[8 + ko] = 1.0f;   // allocation_mask
            }
        }
    }
    __syncthreads();
    const float g = sGate;
    {
        float w0 = Wc[o * 256 + tid] * g;
        float w1 = Wc[o * 256 + 128 + tid] * g;
        sWc[tid] = w0;
        sWc[128 + tid] = w1;
    }
    __syncthreads();

    float acc[8] = {0.f, 0.f, 0.f, 0.f, 0.f, 0.f, 0.f, 0.f};
#pragma unroll 16
    for (int i = 0; i < 256; ++i)
        acc[i & 7] += sWc[i] * Wp[i * 256 + col];
    float r = ((acc[0] + acc[1]) + (acc[2] + acc[3])) +
              ((acc[4] + acc[5]) + (acc[6] + acc[7]));
    g_W1[o * 256 + col] = r;
    g_Bh[o * 256 + col] = __float2half_rn(r);

    if (h == 0) {
        float p = sWc[tid] * bp[tid] + sWc[128 + tid] * bp[128 + tid];
        p = warp_sum(p);
        if ((tid & 31) == 0) sRed[tid >> 5] = p;
        __syncthreads();
        if (tid == 0)
            g_bias[o] = (sRed[0] + sRed[1]) + (sRed[2] + sRed[3]);
    }
}

// Block (o, h): W2[o, col] = sum_i Wo[o,i] * W1[i, col]; h==0 computes c2[o].
__global__ void __launch_bounds__(128, 8)
prep_w2(const float* __restrict__ Wo, const float* __restrict__ bo) {
    __shared__ float sWo[256];
    __shared__ float sRed[4];
    const int o   = blockIdx.x >> 1;
    const int h   = blockIdx.x & 1;
    const int tid = threadIdx.x;
    const int col = h * 128 + tid;

    sWo[tid]       = Wo[o * 256 + tid];
    sWo[128 + tid] = Wo[o * 256 + 128 + tid];
    __syncthreads();

    float acc[8] = {0.f, 0.f, 0.f, 0.f, 0.f, 0.f, 0.f, 0.f};
#pragma unroll 16
    for (int i = 0; i < 256; ++i)
        acc[i & 7] += sWo[i] * g_W1[i * 256 + col];
    float r = ((acc[0] + acc[1]) + (acc[2] + acc[3])) +
              ((acc[4] + acc[5]) + (acc[6] + acc[7]));
    g_Bh[(256 + o) * 256 + col] = __float2half_rn(r);

    if (h == 0) {
        float p = sWo[tid] * g_bias[tid] + sWo[128 + tid] * g_bias[128 + tid];
        p = warp_sum(p);
        if ((tid & 31) == 0) sRed[tid >> 5] = p;
        __syncthreads();
        if (tid == 0)
            g_bias[256 + o] = (sRed[0] + sRed[1]) + (sRed[2] + sRed[3]) + bo[o];
    }
}

// ============================================================================
// Main fused GEMM: C[131072 x 512] = x[131072 x 256] @ B^T, single fp16 pass,
// HMMA m16n8k16, fp32 accumulate.
// CTA: 128x256, 16 warps (4M x 4N, warp tile 32x64), block 512, 1 CTA/SM.
// B persistent in smem. A: LDG->regs (static pre[4]) -> fp16 -> STS,
// 2-stage ring of K=64 chunks, prefetch distance 1, one sync per chunk (4 total).
// ============================================================================
__global__ void __launch_bounds__(512, 1)
fused_main(const float* __restrict__ x, float* __restrict__ out, int Brows) {
    extern __shared__ char smem[];
    const uint32_t sb = smem_to_u32(smem);
    const int tid  = threadIdx.x;
    const int wid  = tid >> 5, lane = tid & 31;
    const int nt   = blockIdx.x & 1;        // 0: combined cols, 1: out cols
    const int mt   = blockIdx.x >> 1;       // M-tile
    const int wm   = wid & 3;               // 4 M-warps of 32 rows
    const int wn   = wid >> 2;              // 4 N-warps of 64 cols

    const float*  xbase = x + (size_t)mt * BM * DIN;
    const __half* Bg    = g_Bh + (size_t)nt * BN * DIN;

    // ---- persistent B tile (256 rows x full K) + bias via cp.async ----
    {
        const uint32_t bd = sb + SM_B;
#pragma unroll
        for (int i = 0; i < 16; ++i) {
            int idx = tid + 512 * i;            // 8192 x 16B
            int row = idx >> 5, kseg = idx & 31;
            cp_async16(bd + row * B_STRIDE + kseg * 16, Bg + row * DIN + kseg * 8);
        }
        if (tid < 64)
            cp_async16(sb + SM_BIAS + tid * 16, g_bias + nt * BN + tid * 4);
        cp_commit();
    }

    float acc[2][8][4];
#pragma unroll
    for (int m = 0; m < 2; m++)
#pragma unroll
        for (int n = 0; n < 8; n++)
#pragma unroll
            for (int k = 0; k < 4; k++) acc[m][n][k] = 0.f;

    // per-thread x prefetch: 4 float4 per K=64 chunk (static indexing)
    // 512 threads: 4 threads/row, each owns 4 consecutive 16B segs of 16.
    const int prow  = tid >> 2;                  // row 0..127
    const int pseg0 = (tid & 3) * 4;             // segs {0..3},{4..7},{8..11},{12..15}
    const float* xrow = xbase + prow * DIN + pseg0 * 4;
    float4 pre[4];
#pragma unroll
    for (int j = 0; j < 4; ++j)
        pre[j] = *(const float4*)(xrow + j * 4);

    const int arow  = wm * 32 + (lane & 15);
    const uint32_t acolb = ((lane >> 4) & 1) * 16;
    const int brow0 = wn * 64 + ((lane & 7) | ((lane >> 4) << 3));
    const uint32_t bcolb = ((lane >> 3) & 1) * 16;

#pragma unroll 1
    for (int c = 0; c < NCHUNK; ++c) {
        const int s = c & 1;

        // ---- convert prefetched fp32 -> fp16, STS to A stage s ----
        {
            char* As = smem + SM_A + s * A_STAGE;
#pragma unroll
            for (int j = 0; j < 4; ++j) {
                __half h0 = __float2half_rn(pre[j].x), h1 = __float2half_rn(pre[j].y);
                __half h2 = __float2half_rn(pre[j].z), h3 = __float2half_rn(pre[j].w);
                uint2 hp;
                hp.x = (uint32_t)__half_as_ushort(h0) | ((uint32_t)__half_as_ushort(h1) << 16);
                hp.y = (uint32_t)__half_as_ushort(h2) | ((uint32_t)__half_as_ushort(h3) << 16);
                *(uint2*)(As + prow * A_STRIDE + (pseg0 + j) * 8) = hp;
            }
        }
        if (c == 0) cp_wait0();     // B + bias resident before first ldmatrix
        __syncthreads();

        // ---- prefetch next chunk (LDG in flight under 64 MMAs) ----
        if (c + 1 < NCHUNK) {
#pragma unroll
            for (int j = 0; j < 4; ++j)
                pre[j] = *(const float4*)(xrow + (c + 1) * BK + j * 4);
        }

        // ---- 4 k16 steps of MMA ----
        const uint32_t abase = sb + SM_A + s * A_STAGE;
        const uint32_t bks   = sb + SM_B + (uint32_t)(c * 128);  // c*64 halves = c*128 bytes
#pragma unroll
        for (int ks = 0; ks < 4; ++ks) {
            uint32_t af[2][4], bf[4][4];
#pragma unroll
            for (int m = 0; m < 2; ++m)
                ldmx4(af[m], abase + (uint32_t)((arow + m * 16) * A_STRIDE) + acolb + ks * 32);
#pragma unroll
            for (int p = 0; p < 4; ++p)
                ldmx4(bf[p], bks + (uint32_t)((brow0 + p * 16) * B_STRIDE) + bcolb + ks * 32);
#pragma unroll
            for (int m = 0; m < 2; ++m)
#pragma unroll
                for (int n = 0; n < 8; ++n)
                    mma16816(acc[m][n], af[m], &bf[n >> 1][(n & 1) * 2]);
        }
    }

    // ---- epilogue: add fused bias (smem), write this CTA's output half ----
    const float* bias_s = (const float*)(smem + SM_BIAS);
    // nt==0 -> combined block (second Brows*256 of out); nt==1 -> out block (first)
    float* hbase = out + (nt ? (size_t)0 : (size_t)Brows * 256);
#pragma unroll
    for (int m = 0; m < 2; ++m) {
        const int row = mt * BM + wm * 32 + m * 16 + (lane >> 2);
        float* rp = hbase + (size_t)row * 256;
#pragma unroll
        for (int n = 0; n < 8; ++n) {
            const int ln = wn * 64 + n * 8 + (lane & 3) * 2;   // 0..255 column
            const float b0 = bias_s[ln], b1 = bias_s[ln + 1];
            *(float2*)(rp + ln)           = make_float2(acc[m][n][0] + b0, acc[m][n][1] + b1);
            *(float2*)(rp + ln + 8 * 256) = make_float2(acc[m][n][2] + b0, acc[m][n][3] + b1);
        }
    }
}

// ============================================================================
// kernel_launch
// ============================================================================
extern "C" void kernel_launch(void* const* d_in, const int* in_sizes, int n_in,
                              void* d_out, int out_size) {
    const float* x    = (const float*)d_in[0];
    const float* Wp   = (const float*)d_in[1];
    const float* bp   = (const float*)d_in[2];
    const float* pre  = (const float*)d_in[3];
    const float* post = (const float*)d_in[4];
    const float* Wc   = (const float*)d_in[5];
    const float* Wo   = (const float*)d_in[6];
    const float* bo   = (const float*)d_in[7];
    float* out = (float*)d_out;
    const int Brows = in_sizes[0] / 256;   // 131072

    cudaFuncSetAttribute(fused_main, cudaFuncAttributeMaxDynamicSharedMemorySize, SMEM_SZ);

    prep_w1<<<512, 128>>>(Wc, Wp, bp, pre, post, out + (size_t)2 * Brows * 256);
    prep_w2<<<512, 128>>>(Wo, bo);
    fused_main<<<(Brows / BM) * 2, 512, SMEM_SZ>>>(x, out, Brows);
}